// round 6
// baseline (speedup 1.0000x reference)
#include <cuda_runtime.h>
#include <cuda_bf16.h>

// Problem dims (fixed by the reference)
#define BB   8
#define NN   1024
#define DD   256
#define HH   512
#define MMd  256
#define OOd  256
#define ROWS (BB*NN)          // 8192

// ---------------------------------------------------------------------------
// Scratch (device globals — allocation-free per harness rules)
// ---------------------------------------------------------------------------
__device__ float g_xproj[(size_t)ROWS * 4 * HH];   // 64 MB
__device__ float g_h    [(size_t)ROWS * HH];       // 16 MB
__device__ float g_ax   [(size_t)ROWS * MMd];      // 8 MB  (also reused as z)
__device__ float g_av   [(size_t)ROWS * MMd];      // 8 MB
__device__ float g_scores[(size_t)BB * NN * NN];   // 32 MB (w in-place)
__device__ float g_sagg [(size_t)ROWS * HH];       // 16 MB
__device__ float g_t1   [(size_t)ROWS * MMd];      // 8 MB
__device__ float g_agg  [(size_t)ROWS * OOd];      // 8 MB
__device__ float g_rmask[ROWS];
__device__ unsigned g_bar_count;
__device__ unsigned g_bar_sense;

__global__ void reset_barrier_kernel() {
    g_bar_count = 0u;
    g_bar_sense = 0u;
}

// ---------------------------------------------------------------------------
// Generic fp32 tiled GEMM:  C = epilogue( A @ B(^T) + bias )
//   A: [M,K] row-major, lda
//   TRANSB=true : B is W [N,K] row-major (torch Linear weight), ldb = row stride
//   TRANSB=false: B is [K,N] row-major, ldb
// Tile 128x128x16, 256 threads, 8x8 microtile. Dims must divide exactly
// (all shapes in this problem do).
// ---------------------------------------------------------------------------
template<bool TRANSB, bool RELU, bool ACCUM, bool RMASK>
__global__ void __launch_bounds__(256) gemm_k(
    const float* __restrict__ A, const float* __restrict__ B,
    const float* __restrict__ bias, const float* __restrict__ rmask,
    float* __restrict__ C,
    int K, int lda, int ldb, int ldc,
    long long sA, long long sB, long long sC)
{
    __shared__ __align__(16) float As[16][132];
    __shared__ __align__(16) float Bs[16][132];

    const int bz = blockIdx.z;
    A += (long long)bz * sA;
    B += (long long)bz * sB;
    C += (long long)bz * sC;

    const int m0 = blockIdx.y * 128;
    const int n0 = blockIdx.x * 128;
    const int tid = threadIdx.x;
    const int tx = tid & 15;   // -> n
    const int ty = tid >> 4;   // -> m

    float acc[8][8];
#pragma unroll
    for (int i = 0; i < 8; i++)
#pragma unroll
        for (int j = 0; j < 8; j++) acc[i][j] = 0.f;

    for (int k0 = 0; k0 < K; k0 += 16) {
        // ---- load A tile (transpose into As[k][m]) ----
#pragma unroll
        for (int ii = 0; ii < 2; ii++) {
            int f   = tid + ii * 256;          // 0..511 float4 slots (128 rows x 4)
            int row = f >> 2;
            int cg  = (f & 3) << 2;
            float4 v = *(const float4*)(A + (long long)(m0 + row) * lda + k0 + cg);
            As[cg + 0][row] = v.x;
            As[cg + 1][row] = v.y;
            As[cg + 2][row] = v.z;
            As[cg + 3][row] = v.w;
        }
        // ---- load B tile ----
        if (TRANSB) {
#pragma unroll
            for (int ii = 0; ii < 2; ii++) {
                int f   = tid + ii * 256;
                int row = f >> 2;              // n index
                int cg  = (f & 3) << 2;        // k index
                float4 v = *(const float4*)(B + (long long)(n0 + row) * ldb + k0 + cg);
                Bs[cg + 0][row] = v.x;
                Bs[cg + 1][row] = v.y;
                Bs[cg + 2][row] = v.z;
                Bs[cg + 3][row] = v.w;
            }
        } else {
#pragma unroll
            for (int ii = 0; ii < 2; ii++) {
                int f  = tid + ii * 256;
                int kr = f >> 5;               // k index (16 rows x 32 float4)
                int nc = (f & 31) << 2;        // n index
                *(float4*)&Bs[kr][nc] =
                    *(const float4*)(B + (long long)(k0 + kr) * ldb + n0 + nc);
            }
        }
        __syncthreads();

#pragma unroll
        for (int kk = 0; kk < 16; kk++) {
            float a[8], b[8];
            *(float4*)&a[0] = *(const float4*)&As[kk][ty * 8];
            *(float4*)&a[4] = *(const float4*)&As[kk][ty * 8 + 4];
            *(float4*)&b[0] = *(const float4*)&Bs[kk][tx * 8];
            *(float4*)&b[4] = *(const float4*)&Bs[kk][tx * 8 + 4];
#pragma unroll
            for (int i = 0; i < 8; i++)
#pragma unroll
                for (int j = 0; j < 8; j++)
                    acc[i][j] = fmaf(a[i], b[j], acc[i][j]);
        }
        __syncthreads();
    }

    // ---- epilogue ----
#pragma unroll
    for (int i = 0; i < 8; i++) {
        int row = m0 + ty * 8 + i;
        float rm = 1.f;
        if (RMASK) rm = rmask[row];
#pragma unroll
        for (int jv = 0; jv < 2; jv++) {
            int col = n0 + tx * 8 + jv * 4;
            float4 v = make_float4(acc[i][jv * 4 + 0], acc[i][jv * 4 + 1],
                                   acc[i][jv * 4 + 2], acc[i][jv * 4 + 3]);
            if (bias) {
                float4 bb = *(const float4*)(bias + col);
                v.x += bb.x; v.y += bb.y; v.z += bb.z; v.w += bb.w;
            }
            float4* cp = (float4*)(C + (long long)row * ldc + col);
            if (ACCUM) {
                float4 c0 = *cp;
                v.x += c0.x; v.y += c0.y; v.z += c0.z; v.w += c0.w;
            }
            if (RELU) {
                v.x = fmaxf(v.x, 0.f); v.y = fmaxf(v.y, 0.f);
                v.z = fmaxf(v.z, 0.f); v.w = fmaxf(v.w, 0.f);
            }
            if (RMASK) { v.x *= rm; v.y *= rm; v.z *= rm; v.w *= rm; }
            *cp = v;
        }
    }
}

// ---------------------------------------------------------------------------
// Persistent LSTM kernel: 128 CTAs x 256 threads, one grid barrier per step.
// CTA k owns hidden units j0=4k..4k+3 (16 gate rows). W_hh slice resident in
// SMEM for all 1024 steps. Warp w computes gate rows {2w,2w+1} for all 8
// batches; butterfly-reduced gate sums land in gsm; 32 threads do the cell
// update and write h(t) to global; software grid barrier publishes it.
// ---------------------------------------------------------------------------
#define LSTM_CTAS 128
#define LSTM_SMEM ((16*512 + 8*512 + 128 + 16 + 32) * 4)   // 49856 B

__global__ void __launch_bounds__(256) lstm_kernel(
    const float* __restrict__ xproj,   // [8192, 2048] (no bias)
    const float* __restrict__ W_hh,    // [2048, 512]
    const float* __restrict__ b_ih,    // [2048]
    const float* __restrict__ b_hh,    // [2048]
    float* __restrict__ h_out)         // [8192, 512], row = b*1024 + t
{
    extern __shared__ __align__(16) float sm[];
    float* Wsm = sm;                    // 16*512
    float* hsm = sm + 16 * 512;         // 8*512
    float* gsm = hsm + 8 * 512;         // 16*8
    float* bsm = gsm + 128;             // 16
    float* csm = bsm + 16;              // 32

    const int tid = threadIdx.x;
    const int cta = blockIdx.x;
    const int j0  = cta * 4;

    // Load W_hh slice: rows q*512 + j0 + jj  (d = q*4 + jj)
    for (int d = 0; d < 16; d++) {
        int q = d >> 2, jj = d & 3;
        const float* src = W_hh + (long long)(q * 512 + j0 + jj) * 512;
        for (int idx = tid; idx < 128; idx += 256)
            *(float4*)&Wsm[d * 512 + idx * 4] = *(const float4*)&src[idx * 4];
    }
    if (tid < 16) {
        int q = tid >> 2, jj = tid & 3;
        int r = q * 512 + j0 + jj;
        bsm[tid] = b_ih[r] + b_hh[r];
    }
    if (tid < 32) csm[tid] = 0.f;
    for (int idx = tid; idx < 8 * 512; idx += 256) hsm[idx] = 0.f;  // h(-1) = 0
    __syncthreads();

    const int w    = tid >> 5;
    const int lane = tid & 31;
    const int d0   = 2 * w;
    const int d1   = d0 + 1;
    const int ub   = tid >> 2;   // batch (for update threads)
    const int ujj  = tid & 3;    // local hidden (for update threads)

    for (int t = 0; t < 1024; t++) {
        // Prefetch this step's x-projection for the update threads
        float xp0 = 0.f, xp1 = 0.f, xp2 = 0.f, xp3 = 0.f;
        if (tid < 32) {
            long long base = (long long)(ub * 1024 + t) * 2048 + j0 + ujj;
            xp0 = __ldg(&xproj[base + 0 * 512]);
            xp1 = __ldg(&xproj[base + 1 * 512]);
            xp2 = __ldg(&xproj[base + 2 * 512]);
            xp3 = __ldg(&xproj[base + 3 * 512]);
        }
        // Stage h(t-1) into SMEM (t=0 uses the zero init)
        if (t > 0) {
#pragma unroll
            for (int ii = 0; ii < 4; ii++) {
                int f  = tid + ii * 256;      // 0..1023 float4 slots
                int b  = f >> 7;              // 128 float4 per batch row
                int kk = (f & 127) * 4;
                *(float4*)&hsm[b * 512 + kk] =
                    *(const float4*)&h_out[(long long)(b * 1024 + t - 1) * 512 + kk];
            }
        }
        __syncthreads();

        // gates(d, b) = sum_k Wsm[d][k] * h[b][k]
        float acc0[8], acc1[8];
#pragma unroll
        for (int b = 0; b < 8; b++) { acc0[b] = 0.f; acc1[b] = 0.f; }
#pragma unroll 4
        for (int i = 0; i < 16; i++) {
            int kk = lane + 32 * i;
            float w0 = Wsm[d0 * 512 + kk];
            float w1 = Wsm[d1 * 512 + kk];
#pragma unroll
            for (int b = 0; b < 8; b++) {
                float hv = hsm[b * 512 + kk];
                acc0[b] = fmaf(w0, hv, acc0[b]);
                acc1[b] = fmaf(w1, hv, acc1[b]);
            }
        }
#pragma unroll
        for (int off = 16; off > 0; off >>= 1) {
#pragma unroll
            for (int b = 0; b < 8; b++) {
                acc0[b] += __shfl_xor_sync(0xffffffffu, acc0[b], off);
                acc1[b] += __shfl_xor_sync(0xffffffffu, acc1[b], off);
            }
        }
        if (lane < 8)        gsm[d0 * 8 + lane]       = acc0[lane];
        else if (lane < 16)  gsm[d1 * 8 + (lane - 8)] = acc1[lane - 8];
        __syncthreads();

        // Cell update (gate order i,f,g,o)
        if (tid < 32) {
            float gi = gsm[(0 * 4 + ujj) * 8 + ub] + xp0 + bsm[0 * 4 + ujj];
            float gf = gsm[(1 * 4 + ujj) * 8 + ub] + xp1 + bsm[1 * 4 + ujj];
            float gg = gsm[(2 * 4 + ujj) * 8 + ub] + xp2 + bsm[2 * 4 + ujj];
            float go = gsm[(3 * 4 + ujj) * 8 + ub] + xp3 + bsm[3 * 4 + ujj];
            float si = 1.f / (1.f + expf(-gi));
            float sf = 1.f / (1.f + expf(-gf));
            float so = 1.f / (1.f + expf(-go));
            float c  = sf * csm[tid] + si * tanhf(gg);
            csm[tid] = c;
            float h  = so * tanhf(c);
            h_out[(long long)(ub * 1024 + t) * 512 + j0 + ujj] = h;
            __threadfence();
        }
        __syncthreads();

        // Grid barrier (monotonic phase; counters reset per launch)
        if (tid == 0) {
            unsigned p = (unsigned)(t + 1);
            unsigned arrived = atomicAdd(&g_bar_count, 1u) + 1u;
            if (arrived == p * (unsigned)LSTM_CTAS) {
                __threadfence();
                atomicExch(&g_bar_sense, p);
            } else {
                while (*(volatile unsigned*)&g_bar_sense < p) { }
            }
            __threadfence();
        }
        __syncthreads();
    }
}

// ---------------------------------------------------------------------------
// Masked softmax over scores rows; writes w in-place and the has-neighbor mask
// ---------------------------------------------------------------------------
__global__ void __launch_bounds__(256) softmax_kernel(
    float* __restrict__ scores, const int* __restrict__ adj,
    float* __restrict__ rmask)
{
    const int r = blockIdx.x;              // 0..8191 == (b*1024 + i)
    const int i = r & (NN - 1);
    float* srow      = scores + (long long)r * NN;
    const int* arow  = adj    + (long long)r * NN;
    const int tid  = threadIdx.x;
    const int lane = tid & 31, wid = tid >> 5;

    float s[4]; int m[4];
    float mx = -1e30f;
    int cnt = 0;
#pragma unroll
    for (int u = 0; u < 4; u++) {
        int j = tid + u * 256;
        float v  = srow[j];
        int   mk = (arow[j] > 0) && (j != i);
        s[u] = v; m[u] = mk;
        if (mk) { mx = fmaxf(mx, v); cnt++; }
    }

    __shared__ float rf[8];
    __shared__ int   ri[8];
    __shared__ float s_mx, s_inv;
    __shared__ int   s_cnt;

#pragma unroll
    for (int off = 16; off; off >>= 1) {
        mx   = fmaxf(mx, __shfl_xor_sync(0xffffffffu, mx, off));
        cnt += __shfl_xor_sync(0xffffffffu, cnt, off);
    }
    if (lane == 0) { rf[wid] = mx; ri[wid] = cnt; }
    __syncthreads();
    if (tid == 0) {
        float m2 = rf[0]; int c2 = ri[0];
        for (int k = 1; k < 8; k++) { m2 = fmaxf(m2, rf[k]); c2 += ri[k]; }
        s_mx = m2; s_cnt = c2;
    }
    __syncthreads();

    if (s_cnt == 0) {
#pragma unroll
        for (int u = 0; u < 4; u++) srow[tid + u * 256] = 0.f;
        if (tid == 0) rmask[r] = 0.f;
        return;
    }
    float mxAll = s_mx;
    float e[4];
    float sum = 0.f;
#pragma unroll
    for (int u = 0; u < 4; u++) {
        e[u] = m[u] ? expf(s[u] - mxAll) : 0.f;
        sum += e[u];
    }
#pragma unroll
    for (int off = 16; off; off >>= 1) sum += __shfl_xor_sync(0xffffffffu, sum, off);
    if (lane == 0) rf[wid] = sum;
    __syncthreads();
    if (tid == 0) {
        float tot = 0.f;
        for (int k = 0; k < 8; k++) tot += rf[k];
        s_inv = 1.f / tot;
    }
    __syncthreads();
    float inv = s_inv;
#pragma unroll
    for (int u = 0; u < 4; u++) srow[tid + u * 256] = e[u] * inv;
    if (tid == 0) rmask[r] = 1.f;
}

// ---------------------------------------------------------------------------
// Launch
// ---------------------------------------------------------------------------
extern "C" void kernel_launch(void* const* d_in, const int* in_sizes, int n_in,
                              void* d_out, int out_size)
{
    const float* feats = (const float*)d_in[0];
    const int*   adj   = (const int*)  d_in[1];
    const float* W_ih  = (const float*)d_in[2];
    const float* W_hh  = (const float*)d_in[3];
    const float* b_ih  = (const float*)d_in[4];
    const float* b_hh  = (const float*)d_in[5];
    const float* gx_W1 = (const float*)d_in[6];
    const float* gx_b1 = (const float*)d_in[7];
    const float* gx_W2 = (const float*)d_in[8];
    const float* gx_b2 = (const float*)d_in[9];
    const float* gz_W1 = (const float*)d_in[10];
    const float* gz_b1 = (const float*)d_in[11];
    const float* gz_W2 = (const float*)d_in[12];
    const float* gz_b2 = (const float*)d_in[13];
    const float* gv_W1 = (const float*)d_in[14];
    const float* gv_b1 = (const float*)d_in[15];
    const float* gv_W2 = (const float*)d_in[16];
    const float* gv_b2 = (const float*)d_in[17];
    const float* gn_W1 = (const float*)d_in[18];
    const float* gn_b1 = (const float*)d_in[19];
    const float* gn_W2 = (const float*)d_in[20];
    const float* gn_b2 = (const float*)d_in[21];
    const float* out_W = (const float*)d_in[22];
    const float* out_b = (const float*)d_in[23];
    float* out = (float*)d_out;

    float *xproj, *h, *ax, *av, *scores, *sagg, *t1, *agg, *rmask;
    cudaGetSymbolAddress((void**)&xproj,  g_xproj);
    cudaGetSymbolAddress((void**)&h,      g_h);
    cudaGetSymbolAddress((void**)&ax,     g_ax);
    cudaGetSymbolAddress((void**)&av,     g_av);
    cudaGetSymbolAddress((void**)&scores, g_scores);
    cudaGetSymbolAddress((void**)&sagg,   g_sagg);
    cudaGetSymbolAddress((void**)&t1,     g_t1);
    cudaGetSymbolAddress((void**)&agg,    g_agg);
    cudaGetSymbolAddress((void**)&rmask,  g_rmask);

    cudaFuncSetAttribute(lstm_kernel,
                         cudaFuncAttributeMaxDynamicSharedMemorySize, LSTM_SMEM);

    const dim3 blk(256);
    const dim3 gSmall(2, 64, 1);   // [8192 x 256] outputs

    // 1. xproj = feats @ W_ih^T            [8192,2048], K=256
    gemm_k<true,false,false,false><<<dim3(16, 64, 1), blk>>>(
        feats, W_ih, nullptr, nullptr, xproj, 256, 256, 256, 2048, 0, 0, 0);

    // 2. LSTM recurrence -> h [8192,512]
    reset_barrier_kernel<<<1, 1>>>();
    lstm_kernel<<<LSTM_CTAS, 256, LSTM_SMEM>>>(xproj, W_hh, b_ih, b_hh, h);

    // 3. ax = mlp_gx(h)
    gemm_k<true,true,false,false><<<gSmall, blk>>>(
        h, gx_W1, gx_b1, nullptr, t1, 512, 512, 512, 256, 0, 0, 0);
    gemm_k<true,false,false,false><<<gSmall, blk>>>(
        t1, gx_W2, gx_b2, nullptr, ax, 256, 256, 256, 256, 0, 0, 0);

    // 4. av = mlp_gv(h)
    gemm_k<true,true,false,false><<<gSmall, blk>>>(
        h, gv_W1, gv_b1, nullptr, t1, 512, 512, 512, 256, 0, 0, 0);
    gemm_k<true,false,false,false><<<gSmall, blk>>>(
        t1, gv_W2, gv_b2, nullptr, av, 256, 256, 256, 256, 0, 0, 0);

    // 5. scores[b] = ax[b] @ av[b]^T       batched [1024,1024], K=256
    gemm_k<true,false,false,false><<<dim3(8, 8, 8), blk>>>(
        ax, av, nullptr, nullptr, scores, 256, 256, 256, 1024,
        (long long)1024 * 256, (long long)1024 * 256, (long long)1024 * 1024);

    // 6. w = masked softmax(scores) (in place) + rmask
    softmax_kernel<<<ROWS, 256>>>(scores, adj, rmask);

    // 7. sagg[b] = w[b] @ h[b]             batched [1024,512], K=1024
    gemm_k<false,false,false,false><<<dim3(4, 8, 8), blk>>>(
        scores, h, nullptr, nullptr, sagg, 1024, 1024, 512, 512,
        (long long)1024 * 1024, (long long)1024 * 512, (long long)1024 * 512);

    // 8. z = mlp_gz(sagg)   (z stored in ax, no longer needed)
    gemm_k<true,true,false,false><<<gSmall, blk>>>(
        sagg, gz_W1, gz_b1, nullptr, t1, 512, 512, 512, 256, 0, 0, 0);
    gemm_k<true,false,false,false><<<gSmall, blk>>>(
        t1, gz_W2, gz_b2, nullptr, ax, 256, 256, 256, 256, 0, 0, 0);

    // 9. agg = mlp_gn(z) * has_nb
    gemm_k<true,true,false,false><<<gSmall, blk>>>(
        ax, gn_W1, gn_b1, nullptr, t1, 256, 256, 256, 256, 0, 0, 0);
    gemm_k<true,false,false,true><<<gSmall, blk>>>(
        t1, gn_W2, gn_b2, rmask, agg, 256, 256, 256, 256, 0, 0, 0);

    // 10. out = h @ out_W[:, :512]^T + out_b ;  out += agg @ out_W[:, 512:]^T
    gemm_k<true,false,false,false><<<gSmall, blk>>>(
        h, out_W, out_b, nullptr, out, 512, 512, 768, 256, 0, 0, 0);
    gemm_k<true,false,true,false><<<gSmall, blk>>>(
        agg, out_W + 512, nullptr, nullptr, out, 256, 256, 768, 256, 0, 0, 0);
}

// round 7
// speedup vs baseline: 2.0329x; 2.0329x over previous
#include <cuda_runtime.h>
#include <cuda_bf16.h>

// Problem dims (fixed by the reference)
#define BB   8
#define NN   1024
#define DD   256
#define HH   512
#define MMd  256
#define OOd  256
#define ROWS (BB*NN)          // 8192

// ---------------------------------------------------------------------------
// Scratch (device globals — allocation-free per harness rules)
// ---------------------------------------------------------------------------
__device__ float g_xproj[(size_t)ROWS * 4 * HH];   // 64 MB
__device__ float g_h    [(size_t)ROWS * HH];       // 16 MB
__device__ float g_ax   [(size_t)ROWS * MMd];      // 8 MB  (also reused as z)
__device__ float g_av   [(size_t)ROWS * MMd];      // 8 MB
__device__ float g_scores[(size_t)BB * NN * NN];   // 32 MB (w in-place)
__device__ float g_sagg [(size_t)ROWS * HH];       // 16 MB
__device__ float g_t1   [(size_t)ROWS * MMd];      // 8 MB
__device__ float g_agg  [(size_t)ROWS * OOd];      // 8 MB
__device__ float g_rmask[ROWS];
__device__ unsigned g_cnt[NN];                     // per-timestep arrival counters

__global__ void reset_cnt_kernel() {
    g_cnt[threadIdx.x] = 0u;
}

// ---------------------------------------------------------------------------
// f32x2 helpers (FFMA2 — only reachable via PTX fma.rn.f32x2)
// ---------------------------------------------------------------------------
__device__ __forceinline__ unsigned long long pk2(float a, float b) {
    unsigned long long r;
    asm("mov.b64 %0, {%1, %2};" : "=l"(r)
        : "r"(__float_as_uint(a)), "r"(__float_as_uint(b)));
    return r;
}
__device__ __forceinline__ void ffma2(unsigned long long& d,
                                      unsigned long long a, unsigned long long b) {
    asm("fma.rn.f32x2 %0, %1, %2, %3;" : "=l"(d) : "l"(a), "l"(b), "l"(d));
}
__device__ __forceinline__ float2 up2(unsigned long long p) {
    unsigned lo, hi;
    asm("mov.b64 {%0, %1}, %2;" : "=r"(lo), "=r"(hi) : "l"(p));
    return make_float2(__uint_as_float(lo), __uint_as_float(hi));
}

// ---------------------------------------------------------------------------
// Generic fp32 tiled GEMM with FFMA2 microkernel:
//   C = epilogue( A @ B(^T) + bias )
// Tile 128x128x16, 256 threads, 8x8 microtile (as 8x4 f32x2 pairs).
// ---------------------------------------------------------------------------
template<bool TRANSB, bool RELU, bool ACCUM, bool RMASK>
__global__ void __launch_bounds__(256) gemm_k(
    const float* __restrict__ A, const float* __restrict__ B,
    const float* __restrict__ bias, const float* __restrict__ rmask,
    float* __restrict__ C,
    int K, int lda, int ldb, int ldc,
    long long sA, long long sB, long long sC)
{
    __shared__ __align__(16) float As[16][132];
    __shared__ __align__(16) float Bs[16][132];

    const int bz = blockIdx.z;
    A += (long long)bz * sA;
    B += (long long)bz * sB;
    C += (long long)bz * sC;

    const int m0 = blockIdx.y * 128;
    const int n0 = blockIdx.x * 128;
    const int tid = threadIdx.x;
    const int tx = tid & 15;   // -> n
    const int ty = tid >> 4;   // -> m

    unsigned long long acc2[8][4];
#pragma unroll
    for (int i = 0; i < 8; i++)
#pragma unroll
        for (int j = 0; j < 4; j++) acc2[i][j] = 0ull;

    for (int k0 = 0; k0 < K; k0 += 16) {
        // ---- load A tile (transpose into As[k][m]) ----
#pragma unroll
        for (int ii = 0; ii < 2; ii++) {
            int f   = tid + ii * 256;
            int row = f >> 2;
            int cg  = (f & 3) << 2;
            float4 v = *(const float4*)(A + (long long)(m0 + row) * lda + k0 + cg);
            As[cg + 0][row] = v.x;
            As[cg + 1][row] = v.y;
            As[cg + 2][row] = v.z;
            As[cg + 3][row] = v.w;
        }
        // ---- load B tile ----
        if (TRANSB) {
#pragma unroll
            for (int ii = 0; ii < 2; ii++) {
                int f   = tid + ii * 256;
                int row = f >> 2;              // n index
                int cg  = (f & 3) << 2;        // k index
                float4 v = *(const float4*)(B + (long long)(n0 + row) * ldb + k0 + cg);
                Bs[cg + 0][row] = v.x;
                Bs[cg + 1][row] = v.y;
                Bs[cg + 2][row] = v.z;
                Bs[cg + 3][row] = v.w;
            }
        } else {
#pragma unroll
            for (int ii = 0; ii < 2; ii++) {
                int f  = tid + ii * 256;
                int kr = f >> 5;
                int nc = (f & 31) << 2;
                *(float4*)&Bs[kr][nc] =
                    *(const float4*)(B + (long long)(k0 + kr) * ldb + n0 + nc);
            }
        }
        __syncthreads();

#pragma unroll
        for (int kk = 0; kk < 16; kk++) {
            float a[8];
            *(float4*)&a[0] = *(const float4*)&As[kk][ty * 8];
            *(float4*)&a[4] = *(const float4*)&As[kk][ty * 8 + 4];
            ulonglong2 b01 = *(const ulonglong2*)&Bs[kk][tx * 8];
            ulonglong2 b23 = *(const ulonglong2*)&Bs[kk][tx * 8 + 4];
            unsigned long long bp0 = b01.x, bp1 = b01.y, bp2 = b23.x, bp3 = b23.y;
#pragma unroll
            for (int i = 0; i < 8; i++) {
                unsigned long long ap = pk2(a[i], a[i]);
                ffma2(acc2[i][0], ap, bp0);
                ffma2(acc2[i][1], ap, bp1);
                ffma2(acc2[i][2], ap, bp2);
                ffma2(acc2[i][3], ap, bp3);
            }
        }
        __syncthreads();
    }

    // ---- epilogue ----
#pragma unroll
    for (int i = 0; i < 8; i++) {
        int row = m0 + ty * 8 + i;
        float rm = 1.f;
        if (RMASK) rm = rmask[row];
#pragma unroll
        for (int jv = 0; jv < 2; jv++) {
            int col = n0 + tx * 8 + jv * 4;
            float2 p0 = up2(acc2[i][jv * 2 + 0]);
            float2 p1 = up2(acc2[i][jv * 2 + 1]);
            float4 v = make_float4(p0.x, p0.y, p1.x, p1.y);
            if (bias) {
                float4 bb = *(const float4*)(bias + col);
                v.x += bb.x; v.y += bb.y; v.z += bb.z; v.w += bb.w;
            }
            float4* cp = (float4*)(C + (long long)row * ldc + col);
            if (ACCUM) {
                float4 c0 = *cp;
                v.x += c0.x; v.y += c0.y; v.z += c0.z; v.w += c0.w;
            }
            if (RELU) {
                v.x = fmaxf(v.x, 0.f); v.y = fmaxf(v.y, 0.f);
                v.z = fmaxf(v.z, 0.f); v.w = fmaxf(v.w, 0.f);
            }
            if (RMASK) { v.x *= rm; v.y *= rm; v.z *= rm; v.w *= rm; }
            *cp = v;
        }
    }
}

// ---------------------------------------------------------------------------
// Persistent LSTM kernel: 128 CTAs x 256 threads.
// CTA k owns hidden units j0=4k..4k+3 (16 gate rows). W_hh slice (32 KB)
// resident in SMEM for all 1024 steps.
// Warp w (rg=w>>1, bg=w&1) computes gate rows rg*4..rg*4+3 for batches
// bg*4..bg*4+3 over the full K=512, using float4 k-quads + FFMA2.
// Cross-CTA sync: per-step counter, red.release arrive / ld.acquire poll.
// ---------------------------------------------------------------------------
#define LSTM_CTAS 128
#define LSTM_SMEM ((16*512 + 8*512 + 128 + 16 + 32) * 4)   // 49856 B

__global__ void __launch_bounds__(256) lstm_kernel(
    const float* __restrict__ xproj,   // [8192, 2048] (no bias)
    const float* __restrict__ W_hh,    // [2048, 512]
    const float* __restrict__ b_ih,    // [2048]
    const float* __restrict__ b_hh,    // [2048]
    float* __restrict__ h_out)         // [8192, 512], row = b*1024 + t
{
    extern __shared__ __align__(16) float sm[];
    float* Wsm = sm;                    // 16*512
    float* hsm = sm + 16 * 512;         // 8*512
    float* gsm = hsm + 8 * 512;         // 16*8
    float* bsm = gsm + 128;             // 16
    float* csm = bsm + 16;              // 32

    const int tid = threadIdx.x;
    const int cta = blockIdx.x;
    const int j0  = cta * 4;

    // Load W_hh slice: row d = q*4 + jj holds W_hh row (q*512 + j0 + jj)
    for (int d = 0; d < 16; d++) {
        int q = d >> 2, jj = d & 3;
        const float* src = W_hh + (long long)(q * 512 + j0 + jj) * 512;
        for (int idx = tid; idx < 128; idx += 256)
            *(float4*)&Wsm[d * 512 + idx * 4] = *(const float4*)&src[idx * 4];
    }
    if (tid < 16) {
        int q = tid >> 2, jj = tid & 3;
        int r = q * 512 + j0 + jj;
        bsm[tid] = b_ih[r] + b_hh[r];
    }
    if (tid < 32) csm[tid] = 0.f;
    for (int idx = tid; idx < 8 * 512; idx += 256) hsm[idx] = 0.f;  // h(-1)=0
    __syncthreads();

    const int w    = tid >> 5;
    const int lane = tid & 31;
    const int rg   = w >> 1;           // row group: rows rg*4 .. rg*4+3
    const int bg   = w & 1;            // batch group: batches bg*4 .. bg*4+3
    const float* Wbase = Wsm + rg * 4 * 512;
    const float* Hbase = hsm + bg * 4 * 512;
    const int ub   = tid >> 2;         // update: batch
    const int ujj  = tid & 3;          // update: local hidden unit

    for (int t = 0; t < 1024; t++) {
        // Wait for h(t-1) from all CTAs (acquire pairs with producers' release)
        if (t > 0 && tid == 0) {
            const unsigned* cp = &g_cnt[t - 1];
            unsigned v;
            do {
                asm volatile("ld.acquire.gpu.u32 %0, [%1];"
                             : "=r"(v) : "l"(cp) : "memory");
            } while (v < (unsigned)LSTM_CTAS);
        }
        __syncthreads();

        // Prefetch this step's x-projection for the update threads
        float xp0 = 0.f, xp1 = 0.f, xp2 = 0.f, xp3 = 0.f;
        if (tid < 32) {
            long long base = (long long)(ub * 1024 + t) * 2048 + j0 + ujj;
            xp0 = __ldg(&xproj[base + 0 * 512]);
            xp1 = __ldg(&xproj[base + 1 * 512]);
            xp2 = __ldg(&xproj[base + 2 * 512]);
            xp3 = __ldg(&xproj[base + 3 * 512]);
        }
        // Stage h(t-1) into SMEM (t=0 uses the zero init)
        if (t > 0) {
#pragma unroll
            for (int ii = 0; ii < 4; ii++) {
                int f  = tid + ii * 256;
                int b  = f >> 7;
                int kk = (f & 127) * 4;
                *(float4*)&hsm[b * 512 + kk] =
                    *(const float4*)&h_out[(long long)(b * 1024 + t - 1) * 512 + kk];
            }
        }
        __syncthreads();

        // gates(d, b) = sum_k Wsm[d][k] * h[b][k]   (4 rows x 4 batches / warp)
        unsigned long long acc[4][4];
#pragma unroll
        for (int rr = 0; rr < 4; rr++)
#pragma unroll
            for (int bb = 0; bb < 4; bb++) acc[rr][bb] = 0ull;

#pragma unroll
        for (int i = 0; i < 4; i++) {
            int kk = lane * 4 + i * 128;
            float4 wv[4], hv[4];
#pragma unroll
            for (int rr = 0; rr < 4; rr++)
                wv[rr] = *(const float4*)&Wbase[rr * 512 + kk];
#pragma unroll
            for (int bb = 0; bb < 4; bb++)
                hv[bb] = *(const float4*)&Hbase[bb * 512 + kk];
#pragma unroll
            for (int rr = 0; rr < 4; rr++) {
                unsigned long long w01 = pk2(wv[rr].x, wv[rr].y);
                unsigned long long w23 = pk2(wv[rr].z, wv[rr].w);
#pragma unroll
                for (int bb = 0; bb < 4; bb++) {
                    ffma2(acc[rr][bb], w01, pk2(hv[bb].x, hv[bb].y));
                    ffma2(acc[rr][bb], w23, pk2(hv[bb].z, hv[bb].w));
                }
            }
        }

        float val[4][4];
#pragma unroll
        for (int rr = 0; rr < 4; rr++)
#pragma unroll
            for (int bb = 0; bb < 4; bb++) {
                float2 p = up2(acc[rr][bb]);
                val[rr][bb] = p.x + p.y;
            }
#pragma unroll
        for (int off = 16; off > 0; off >>= 1)
#pragma unroll
            for (int rr = 0; rr < 4; rr++)
#pragma unroll
                for (int bb = 0; bb < 4; bb++)
                    val[rr][bb] += __shfl_xor_sync(0xffffffffu, val[rr][bb], off);
        if (lane == 0) {
#pragma unroll
            for (int rr = 0; rr < 4; rr++)
#pragma unroll
                for (int bb = 0; bb < 4; bb++)
                    gsm[(rg * 4 + rr) * 8 + bg * 4 + bb] = val[rr][bb];
        }
        __syncthreads();

        // Cell update (gate order i,f,g,o); fast sigmoid/tanh via MUFU
        if (tid < 32) {
            float gi = gsm[(0 * 4 + ujj) * 8 + ub] + xp0 + bsm[0 * 4 + ujj];
            float gf = gsm[(1 * 4 + ujj) * 8 + ub] + xp1 + bsm[1 * 4 + ujj];
            float gg = gsm[(2 * 4 + ujj) * 8 + ub] + xp2 + bsm[2 * 4 + ujj];
            float go = gsm[(3 * 4 + ujj) * 8 + ub] + xp3 + bsm[3 * 4 + ujj];
            float si = __fdividef(1.f, 1.f + __expf(-gi));
            float sf = __fdividef(1.f, 1.f + __expf(-gf));
            float so = __fdividef(1.f, 1.f + __expf(-go));
            float tg = 2.f * __fdividef(1.f, 1.f + __expf(-2.f * gg)) - 1.f;
            float c  = sf * csm[tid] + si * tg;
            csm[tid] = c;
            float tc = 2.f * __fdividef(1.f, 1.f + __expf(-2.f * c)) - 1.f;
            float h  = so * tc;
            h_out[(long long)(ub * 1024 + t) * 512 + j0 + ujj] = h;
        }
        __syncthreads();   // establishes HB: h writes -> tid0's release below

        if (tid == 0) {
            const unsigned* cp = &g_cnt[t];
            asm volatile("red.release.gpu.add.u32 [%0], %1;"
                         :: "l"(cp), "r"(1u) : "memory");
        }
    }
}

// ---------------------------------------------------------------------------
// Masked softmax over scores rows; writes w in-place and the has-neighbor mask
// ---------------------------------------------------------------------------
__global__ void __launch_bounds__(256) softmax_kernel(
    float* __restrict__ scores, const int* __restrict__ adj,
    float* __restrict__ rmask)
{
    const int r = blockIdx.x;              // 0..8191 == (b*1024 + i)
    const int i = r & (NN - 1);
    float* srow      = scores + (long long)r * NN;
    const int* arow  = adj    + (long long)r * NN;
    const int tid  = threadIdx.x;
    const int lane = tid & 31, wid = tid >> 5;

    float s[4]; int m[4];
    float mx = -1e30f;
    int cnt = 0;
#pragma unroll
    for (int u = 0; u < 4; u++) {
        int j = tid + u * 256;
        float v  = srow[j];
        int   mk = (arow[j] > 0) && (j != i);
        s[u] = v; m[u] = mk;
        if (mk) { mx = fmaxf(mx, v); cnt++; }
    }

    __shared__ float rf[8];
    __shared__ int   ri[8];
    __shared__ float s_mx, s_inv;
    __shared__ int   s_cnt;

#pragma unroll
    for (int off = 16; off; off >>= 1) {
        mx   = fmaxf(mx, __shfl_xor_sync(0xffffffffu, mx, off));
        cnt += __shfl_xor_sync(0xffffffffu, cnt, off);
    }
    if (lane == 0) { rf[wid] = mx; ri[wid] = cnt; }
    __syncthreads();
    if (tid == 0) {
        float m2 = rf[0]; int c2 = ri[0];
        for (int k = 1; k < 8; k++) { m2 = fmaxf(m2, rf[k]); c2 += ri[k]; }
        s_mx = m2; s_cnt = c2;
    }
    __syncthreads();

    if (s_cnt == 0) {
#pragma unroll
        for (int u = 0; u < 4; u++) srow[tid + u * 256] = 0.f;
        if (tid == 0) rmask[r] = 0.f;
        return;
    }
    float mxAll = s_mx;
    float e[4];
    float sum = 0.f;
#pragma unroll
    for (int u = 0; u < 4; u++) {
        e[u] = m[u] ? expf(s[u] - mxAll) : 0.f;
        sum += e[u];
    }
#pragma unroll
    for (int off = 16; off; off >>= 1) sum += __shfl_xor_sync(0xffffffffu, sum, off);
    if (lane == 0) rf[wid] = sum;
    __syncthreads();
    if (tid == 0) {
        float tot = 0.f;
        for (int k = 0; k < 8; k++) tot += rf[k];
        s_inv = 1.f / tot;
    }
    __syncthreads();
    float inv = s_inv;
#pragma unroll
    for (int u = 0; u < 4; u++) srow[tid + u * 256] = e[u] * inv;
    if (tid == 0) rmask[r] = 1.f;
}

// ---------------------------------------------------------------------------
// Launch
// ---------------------------------------------------------------------------
extern "C" void kernel_launch(void* const* d_in, const int* in_sizes, int n_in,
                              void* d_out, int out_size)
{
    const float* feats = (const float*)d_in[0];
    const int*   adj   = (const int*)  d_in[1];
    const float* W_ih  = (const float*)d_in[2];
    const float* W_hh  = (const float*)d_in[3];
    const float* b_ih  = (const float*)d_in[4];
    const float* b_hh  = (const float*)d_in[5];
    const float* gx_W1 = (const float*)d_in[6];
    const float* gx_b1 = (const float*)d_in[7];
    const float* gx_W2 = (const float*)d_in[8];
    const float* gx_b2 = (const float*)d_in[9];
    const float* gz_W1 = (const float*)d_in[10];
    const float* gz_b1 = (const float*)d_in[11];
    const float* gz_W2 = (const float*)d_in[12];
    const float* gz_b2 = (const float*)d_in[13];
    const float* gv_W1 = (const float*)d_in[14];
    const float* gv_b1 = (const float*)d_in[15];
    const float* gv_W2 = (const float*)d_in[16];
    const float* gv_b2 = (const float*)d_in[17];
    const float* gn_W1 = (const float*)d_in[18];
    const float* gn_b1 = (const float*)d_in[19];
    const float* gn_W2 = (const float*)d_in[20];
    const float* gn_b2 = (const float*)d_in[21];
    const float* out_W = (const float*)d_in[22];
    const float* out_b = (const float*)d_in[23];
    float* out = (float*)d_out;

    float *xproj, *h, *ax, *av, *scores, *sagg, *t1, *agg, *rmask;
    cudaGetSymbolAddress((void**)&xproj,  g_xproj);
    cudaGetSymbolAddress((void**)&h,      g_h);
    cudaGetSymbolAddress((void**)&ax,     g_ax);
    cudaGetSymbolAddress((void**)&av,     g_av);
    cudaGetSymbolAddress((void**)&scores, g_scores);
    cudaGetSymbolAddress((void**)&sagg,   g_sagg);
    cudaGetSymbolAddress((void**)&t1,     g_t1);
    cudaGetSymbolAddress((void**)&agg,    g_agg);
    cudaGetSymbolAddress((void**)&rmask,  g_rmask);

    cudaFuncSetAttribute(lstm_kernel,
                         cudaFuncAttributeMaxDynamicSharedMemorySize, LSTM_SMEM);

    const dim3 blk(256);
    const dim3 gSmall(2, 64, 1);   // [8192 x 256] outputs

    // 1. xproj = feats @ W_ih^T            [8192,2048], K=256
    gemm_k<true,false,false,false><<<dim3(16, 64, 1), blk>>>(
        feats, W_ih, nullptr, nullptr, xproj, 256, 256, 256, 2048, 0, 0, 0);

    // 2. LSTM recurrence -> h [8192,512]
    reset_cnt_kernel<<<1, NN>>>();
    lstm_kernel<<<LSTM_CTAS, 256, LSTM_SMEM>>>(xproj, W_hh, b_ih, b_hh, h);

    // 3. ax = mlp_gx(h)
    gemm_k<true,true,false,false><<<gSmall, blk>>>(
        h, gx_W1, gx_b1, nullptr, t1, 512, 512, 512, 256, 0, 0, 0);
    gemm_k<true,false,false,false><<<gSmall, blk>>>(
        t1, gx_W2, gx_b2, nullptr, ax, 256, 256, 256, 256, 0, 0, 0);

    // 4. av = mlp_gv(h)
    gemm_k<true,true,false,false><<<gSmall, blk>>>(
        h, gv_W1, gv_b1, nullptr, t1, 512, 512, 512, 256, 0, 0, 0);
    gemm_k<true,false,false,false><<<gSmall, blk>>>(
        t1, gv_W2, gv_b2, nullptr, av, 256, 256, 256, 256, 0, 0, 0);

    // 5. scores[b] = ax[b] @ av[b]^T       batched [1024,1024], K=256
    gemm_k<true,false,false,false><<<dim3(8, 8, 8), blk>>>(
        ax, av, nullptr, nullptr, scores, 256, 256, 256, 1024,
        (long long)1024 * 256, (long long)1024 * 256, (long long)1024 * 1024);

    // 6. w = masked softmax(scores) (in place) + rmask
    softmax_kernel<<<ROWS, 256>>>(scores, adj, rmask);

    // 7. sagg[b] = w[b] @ h[b]             batched [1024,512], K=1024
    gemm_k<false,false,false,false><<<dim3(4, 8, 8), blk>>>(
        scores, h, nullptr, nullptr, sagg, 1024, 1024, 512, 512,
        (long long)1024 * 1024, (long long)1024 * 512, (long long)1024 * 512);

    // 8. z = mlp_gz(sagg)   (z stored in ax, no longer needed)
    gemm_k<true,true,false,false><<<gSmall, blk>>>(
        sagg, gz_W1, gz_b1, nullptr, t1, 512, 512, 512, 256, 0, 0, 0);
    gemm_k<true,false,false,false><<<gSmall, blk>>>(
        t1, gz_W2, gz_b2, nullptr, ax, 256, 256, 256, 256, 0, 0, 0);

    // 9. agg = mlp_gn(z) * has_nb
    gemm_k<true,true,false,false><<<gSmall, blk>>>(
        ax, gn_W1, gn_b1, nullptr, t1, 256, 256, 256, 256, 0, 0, 0);
    gemm_k<true,false,false,true><<<gSmall, blk>>>(
        t1, gn_W2, gn_b2, rmask, agg, 256, 256, 256, 256, 0, 0, 0);

    // 10. out = h @ out_W[:, :512]^T + out_b ;  out += agg @ out_W[:, 512:]^T
    gemm_k<true,false,false,false><<<gSmall, blk>>>(
        h, out_W, out_b, nullptr, out, 512, 512, 768, 256, 0, 0, 0);
    gemm_k<true,false,true,false><<<gSmall, blk>>>(
        agg, out_W + 512, nullptr, nullptr, out, 256, 256, 768, 256, 0, 0, 0);
}